// round 4
// baseline (speedup 1.0000x reference)
#include <cuda_runtime.h>

#define T 48
#define E 32
#define C0 64
#define C1 64
#define H1 256
#define H2 128
#define NPRED 12
#define SEQS (16 * 2048)

typedef unsigned long long u64;

__device__ __forceinline__ u64 pk2(float lo, float hi) {
    u64 r; asm("mov.b64 %0,{%1,%2};" : "=l"(r) : "f"(lo), "f"(hi)); return r;
}
__device__ __forceinline__ u64 dupf(float v) {
    u64 r; asm("mov.b64 %0,{%1,%1};" : "=l"(r) : "f"(v)); return r;
}
__device__ __forceinline__ void fma2(u64& d, u64 a, u64 b) {
    asm("fma.rn.f32x2 %0, %1, %2, %0;" : "+l"(d) : "l"(a), "l"(b));
}
__device__ __forceinline__ float2 unpk(u64 v) {
    float2 f; asm("mov.b64 {%0,%1},%2;" : "=f"(f.x), "=f"(f.y) : "l"(v)); return f;
}

// scratch: attention context last row per sequence
__device__ float g_last[SEQS * C1];

// ---------------- Kernel A ----------------
// 2 sequences per CTA-iteration (96 rows). Packed f32x2 FMA, col-pair packing.
// smem layout (float offsets), all even:
//  sWin 0      (2048)
//  sWc  2048   (12288)
//  sWq  14336  (4096)
//  sWk  18432  (4096)
//  sWv  22528  (4096)
//  sB   26624  (320)
//  sx   26944  (96*34  = 3264)   stride 34
//  sh   30208  (100*66 = 6600)   stride 66, padded rows 0,49,50,99 = 0
//  shc  36808  (96*66  = 6336)   stride 66
//  sk   43144  (96*66  = 6336)
//  sv   49480  (96*66  = 6336)
//  sq   55816  (128)
//  ss   55944  (96)
#define SMEM_A_FLOATS 56040

__global__ void __launch_bounds__(256, 1)
kernelA(const float* __restrict__ x,
        const float* __restrict__ Win, const float* __restrict__ bin,
        const float* __restrict__ Wc,  const float* __restrict__ bc,
        const float* __restrict__ Wq,  const float* __restrict__ bq,
        const float* __restrict__ Wk,  const float* __restrict__ bk,
        const float* __restrict__ Wv,  const float* __restrict__ bv)
{
    extern __shared__ float sm[];
    float* sWin = sm;
    float* sWc  = sm + 2048;
    float* sWq  = sm + 14336;
    float* sWk  = sm + 18432;
    float* sWv  = sm + 22528;
    float* sB   = sm + 26624;
    float* sx   = sm + 26944;
    float* sh   = sm + 30208;
    float* shc  = sm + 36808;
    float* sk   = sm + 43144;
    float* sv   = sm + 49480;
    float* sq   = sm + 55816;
    float* ss   = sm + 55944;

    const int tid = threadIdx.x;

    // stage weights once per CTA
    for (int i = tid; i < 2048; i += 256) sWin[i] = Win[i];
    for (int i = tid; i < 12288; i += 256) sWc[i] = Wc[i];
    for (int i = tid; i < 4096; i += 256) {
        sWq[i] = Wq[i]; sWk[i] = Wk[i]; sWv[i] = Wv[i];
    }
    if (tid < 64) {
        sB[tid]       = bin[tid];
        sB[64 + tid]  = bc[tid];
        sB[128 + tid] = bq[tid];
        sB[192 + tid] = bk[tid];
        sB[256 + tid] = bv[tid];
    }
    // zero pad rows of sh (rows 0, 49, 50, 99)
    {
        const int padr[4] = {0, 49, 50, 99};
        int p = padr[tid >> 6], c = tid & 63;
        sh[p * 66 + c] = 0.f;
    }
    __syncthreads();

    const int c8   = (tid & 7) * 8;   // 8-column base (even)
    const int rg   = tid >> 3;        // 0..31 : rows rg, rg+32, rg+64
    const int lane = tid & 31;
    const int warp = tid >> 5;

    // per-thread row indices
    int rr[3], pb[3];
    #pragma unroll
    for (int j = 0; j < 3; j++) {
        rr[j] = rg + 32 * j;                         // global row 0..95
        int pr = rr[j] + 1 + 2 * (rr[j] >= 48);      // padded h row
        pb[j] = pr - 1;                              // conv window base
    }

    for (int pair = blockIdx.x; pair < SEQS / 2; pair += gridDim.x) {
        const int seq0 = pair * 2;

        // ---- 1) stage x for 2 seqs: 96 rows x 32, stride 34 ----
        {
            const float4* xg = (const float4*)(x + (size_t)seq0 * (T * E));
            #pragma unroll
            for (int k = 0; k < 3; k++) {
                int idx = tid + k * 256;             // 0..767
                float4 v = xg[idx];
                int row = idx >> 3, e4 = idx & 7;
                u64* d = (u64*)(sx + row * 34 + e4 * 4);
                d[0] = pk2(v.x, v.y);
                d[1] = pk2(v.z, v.w);
            }
        }
        __syncthreads();

        // ---- 2) in-projection: h[row][c] = x[row]·Win[:,c] + bin ----
        {
            u64 acc[3][4];
            const u64* bb = (const u64*)(sB + c8);
            #pragma unroll
            for (int j = 0; j < 3; j++)
                #pragma unroll
                for (int k = 0; k < 4; k++) acc[j][k] = bb[k];
            #pragma unroll 8
            for (int e = 0; e < E; e++) {
                const ulonglong2* wr = (const ulonglong2*)(sWin + e * C0 + c8);
                ulonglong2 wa = wr[0], wb2 = wr[1];
                #pragma unroll
                for (int j = 0; j < 3; j++) {
                    u64 xv = dupf(sx[rr[j] * 34 + e]);
                    fma2(acc[j][0], xv, wa.x); fma2(acc[j][1], xv, wa.y);
                    fma2(acc[j][2], xv, wb2.x); fma2(acc[j][3], xv, wb2.y);
                }
            }
            #pragma unroll
            for (int j = 0; j < 3; j++) {
                u64* d = (u64*)(sh + (pb[j] + 1) * 66 + c8);
                #pragma unroll
                for (int k = 0; k < 4; k++) d[k] = acc[j][k];
            }
        }
        __syncthreads();

        // ---- 3) conv(k=3, pad=1) + ReLU ----
        {
            u64 acc[3][4];
            const u64* bb = (const u64*)(sB + 64 + c8);
            #pragma unroll
            for (int j = 0; j < 3; j++)
                #pragma unroll
                for (int k = 0; k < 4; k++) acc[j][k] = bb[k];
            #pragma unroll
            for (int dt = 0; dt < 3; dt++) {
                const float* wbase = sWc + dt * C0 * C1 + c8;
                #pragma unroll 8
                for (int ci = 0; ci < C0; ci++) {
                    const ulonglong2* wr = (const ulonglong2*)(wbase + ci * C1);
                    ulonglong2 wa = wr[0], wb2 = wr[1];
                    #pragma unroll
                    for (int j = 0; j < 3; j++) {
                        u64 hv = dupf(sh[(pb[j] + dt) * 66 + ci]);
                        fma2(acc[j][0], hv, wa.x); fma2(acc[j][1], hv, wa.y);
                        fma2(acc[j][2], hv, wb2.x); fma2(acc[j][3], hv, wb2.y);
                    }
                }
            }
            #pragma unroll
            for (int j = 0; j < 3; j++) {
                float* d = shc + rr[j] * 66 + c8;
                #pragma unroll
                for (int k = 0; k < 4; k++) {
                    float2 f = unpk(acc[j][k]);
                    d[2 * k]     = fmaxf(f.x, 0.f);
                    d[2 * k + 1] = fmaxf(f.y, 0.f);
                }
            }
        }
        __syncthreads();

        // ---- 4) k & v projections (fused) ----
        {
            u64 ak[3][4], av[3][4];
            const u64* bkk = (const u64*)(sB + 192 + c8);
            const u64* bvv = (const u64*)(sB + 256 + c8);
            #pragma unroll
            for (int j = 0; j < 3; j++)
                #pragma unroll
                for (int k = 0; k < 4; k++) { ak[j][k] = bkk[k]; av[j][k] = bvv[k]; }
            #pragma unroll 4
            for (int ci = 0; ci < C1; ci++) {
                const ulonglong2* wkr = (const ulonglong2*)(sWk + ci * C1 + c8);
                const ulonglong2* wvr = (const ulonglong2*)(sWv + ci * C1 + c8);
                ulonglong2 ka = wkr[0], kb2 = wkr[1];
                ulonglong2 va = wvr[0], vb2 = wvr[1];
                #pragma unroll
                for (int j = 0; j < 3; j++) {
                    u64 hv = dupf(shc[rr[j] * 66 + ci]);
                    fma2(ak[j][0], hv, ka.x); fma2(ak[j][1], hv, ka.y);
                    fma2(ak[j][2], hv, kb2.x); fma2(ak[j][3], hv, kb2.y);
                    fma2(av[j][0], hv, va.x); fma2(av[j][1], hv, va.y);
                    fma2(av[j][2], hv, vb2.x); fma2(av[j][3], hv, vb2.y);
                }
            }
            #pragma unroll
            for (int j = 0; j < 3; j++) {
                u64* dk = (u64*)(sk + rr[j] * 66 + c8);
                u64* dv = (u64*)(sv + rr[j] * 66 + c8);
                #pragma unroll
                for (int k = 0; k < 4; k++) { dk[k] = ak[j][k]; dv[k] = av[j][k]; }
            }
        }
        // q for last row of each seq (128 threads: s = tid>>6, c = tid&63)
        if (tid < 128) {
            int s = tid >> 6, c = tid & 63;
            float a = sB[128 + c];
            const float* hrow = shc + (s * 48 + 47) * 66;
            #pragma unroll 8
            for (int ci = 0; ci < C1; ci++) a += hrow[ci] * sWq[ci * C1 + c];
            sq[s * 64 + c] = a;
        }
        __syncthreads();

        // ---- 5) scores: 96 of them, warp w handles t = 12w..12w+11 ----
        #pragma unroll
        for (int jj = 0; jj < 12; jj++) {
            int t96 = warp * 12 + jj;
            int s = t96 >= 48;
            const float* kr = sk + t96 * 66;
            const float* qr = sq + s * 64;
            float p = qr[lane] * kr[lane] + qr[lane + 32] * kr[lane + 32];
            #pragma unroll
            for (int o = 16; o > 0; o >>= 1) p += __shfl_xor_sync(0xffffffffu, p, o);
            if (lane == 0) ss[t96] = p * 0.125f;
        }
        __syncthreads();

        // ---- 6) softmax over 48, warps 0/1 handle seqs 0/1 ----
        if (warp < 2) {
            float* sp = ss + warp * 48;
            float a  = sp[lane];
            float b2 = (lane < 16) ? sp[lane + 32] : -1e30f;
            float m = fmaxf(a, b2);
            #pragma unroll
            for (int o = 16; o > 0; o >>= 1) m = fmaxf(m, __shfl_xor_sync(0xffffffffu, m, o));
            float ea = __expf(a - m);
            float eb = (lane < 16) ? __expf(b2 - m) : 0.f;
            float sum = ea + eb;
            #pragma unroll
            for (int o = 16; o > 0; o >>= 1) sum += __shfl_xor_sync(0xffffffffu, sum, o);
            float inv = 1.f / sum;
            sp[lane] = ea * inv;
            if (lane < 16) sp[lane + 32] = eb * inv;
        }
        __syncthreads();

        // ---- 7) ctx last row -> g_last ----
        if (tid < 128) {
            int s = tid >> 6, c = tid & 63;
            const float* sp = ss + s * 48;
            const float* vb = sv + s * 48 * 66 + c;
            float a = 0.f;
            #pragma unroll
            for (int t = 0; t < T; t++) a += sp[t] * vb[t * 66];
            g_last[(size_t)(seq0 + s) * C1 + c] = a;
        }
        __syncthreads();
    }
}

// ---------------- Kernel B: MLP 64 -> 256 -> 128 -> 12 ----------------
// 16 rows per iteration, packed f32x2. W3 read from global (L1-resident, tiny).
// smem: sW1 0 (16384), sW2 16384 (32768), sb1 49152 (256), sb2 49408 (128),
//       sb3 49536 (16), sIn 49552 (16*64=1024), sZ1 50576 (16*258=4128),
//       sZ2 54704 (16*130=2080)  -> 56784 floats = 227136 bytes
#define SMEM_B_FLOATS 56784

__global__ void __launch_bounds__(256, 1)
kernelB(const float* __restrict__ W1, const float* __restrict__ b1,
        const float* __restrict__ W2, const float* __restrict__ b2,
        const float* __restrict__ W3, const float* __restrict__ b3,
        float* __restrict__ out)
{
    extern __shared__ float sm[];
    float* sW1 = sm;
    float* sW2 = sm + 16384;
    float* sb1 = sm + 49152;
    float* sb2 = sm + 49408;
    float* sb3 = sm + 49536;
    float* sIn = sm + 49552;
    float* sZ1 = sm + 50576;
    float* sZ2 = sm + 54704;

    const int tid = threadIdx.x;
    const int lane = tid & 31;
    const int warp = tid >> 5;

    for (int i = tid; i < 16384; i += 256) sW1[i] = W1[i];
    for (int i = tid; i < 32768; i += 256) sW2[i] = W2[i];
    if (tid < 256) sb1[tid] = b1[tid];
    if (tid < 128) sb2[tid] = b2[tid];
    if (tid < 12)  sb3[tid] = b3[tid];
    __syncthreads();

    // z1 mapping: warp -> colhalf ch = warp&1 (128 cols), rowblock rb = warp>>1 (4 rows)
    //             lane -> rl = lane>>4 (rows rb*4+rl, rb*4+rl+2), cl = lane&15 (8 cols)
    const int z1_col = (warp & 1) * 128 + (lane & 15) * 8;
    const int z1_r0  = (warp >> 1) * 4 + (lane >> 4);     // rows z1_r0, z1_r0+2
    // z2 mapping: warp -> colhalf h = warp>>2 (64 cols), rowblock warp&3 (4 rows)
    const int z2_col = (warp >> 2) * 64 + (lane & 7) * 8;
    const int z2_row = (warp & 3) * 4 + (lane >> 3);

    for (int base = blockIdx.x * 16; base < SEQS; base += gridDim.x * 16) {
        // stage 16 rows of g_last -> sIn [16][64]
        {
            const float4* src = (const float4*)(g_last + (size_t)base * C1);
            float4 v = src[tid];               // 256 float4 exactly = 16x64
            int row = tid >> 4, e4 = tid & 15;
            u64* d = (u64*)(sIn + row * 64 + e4 * 4);
            d[0] = pk2(v.x, v.y);
            d[1] = pk2(v.z, v.w);
        }
        __syncthreads();

        // ---- z1 = relu(in @ W1 + b1): 16 x 256 ----
        {
            u64 acc[2][4];
            const u64* bb = (const u64*)(sb1 + z1_col);
            #pragma unroll
            for (int j = 0; j < 2; j++)
                #pragma unroll
                for (int k = 0; k < 4; k++) acc[j][k] = bb[k];
            const float* in0 = sIn + z1_r0 * 64;
            const float* in1 = sIn + (z1_r0 + 2) * 64;
            #pragma unroll 8
            for (int f = 0; f < 64; f++) {
                const ulonglong2* wr = (const ulonglong2*)(sW1 + f * H1 + z1_col);
                ulonglong2 wa = wr[0], wb2 = wr[1];
                u64 x0 = dupf(in0[f]);
                u64 x1 = dupf(in1[f]);
                fma2(acc[0][0], x0, wa.x); fma2(acc[0][1], x0, wa.y);
                fma2(acc[0][2], x0, wb2.x); fma2(acc[0][3], x0, wb2.y);
                fma2(acc[1][0], x1, wa.x); fma2(acc[1][1], x1, wa.y);
                fma2(acc[1][2], x1, wb2.x); fma2(acc[1][3], x1, wb2.y);
            }
            #pragma unroll
            for (int j = 0; j < 2; j++) {
                u64* d = (u64*)(sZ1 + (z1_r0 + 2 * j) * 258 + z1_col);
                #pragma unroll
                for (int k = 0; k < 4; k++) {
                    float2 f2 = unpk(acc[j][k]);
                    d[k] = pk2(fmaxf(f2.x, 0.f), fmaxf(f2.y, 0.f));
                }
            }
        }
        __syncthreads();

        // ---- z2 = relu(z1 @ W2 + b2): 16 x 128 ----
        {
            u64 acc[4];
            const u64* bb = (const u64*)(sb2 + z2_col);
            #pragma unroll
            for (int k = 0; k < 4; k++) acc[k] = bb[k];
            const float* zr = sZ1 + z2_row * 258;
            #pragma unroll 8
            for (int f = 0; f < 256; f++) {
                const ulonglong2* wr = (const ulonglong2*)(sW2 + f * H2 + z2_col);
                ulonglong2 wa = wr[0], wb2 = wr[1];
                u64 zv = dupf(zr[f]);
                fma2(acc[0], zv, wa.x); fma2(acc[1], zv, wa.y);
                fma2(acc[2], zv, wb2.x); fma2(acc[3], zv, wb2.y);
            }
            u64* d = (u64*)(sZ2 + z2_row * 130 + z2_col);
            #pragma unroll
            for (int k = 0; k < 4; k++) {
                float2 f2 = unpk(acc[k]);
                d[k] = pk2(fmaxf(f2.x, 0.f), fmaxf(f2.y, 0.f));
            }
        }
        __syncthreads();

        // ---- pred = z2 @ W3 + b3: 16 x 12, transposed write; W3 from global ----
        if (tid < 192) {
            int r = tid / 12, p = tid % 12;
            const float* zr = sZ2 + r * 130;
            float a = sb3[p];
            #pragma unroll 16
            for (int f = 0; f < 128; f++) a += zr[f] * __ldg(&W3[f * NPRED + p]);
            int seqr = base + r;
            int bb = seqr >> 11;
            int nn = seqr & 2047;
            out[(size_t)bb * (NPRED * 2048) + p * 2048 + nn] = a;
        }
        __syncthreads();
    }
}

extern "C" void kernel_launch(void* const* d_in, const int* in_sizes, int n_in,
                              void* d_out, int out_size)
{
    const float* x     = (const float*)d_in[0];
    const float* W_in  = (const float*)d_in[1];
    const float* b_in  = (const float*)d_in[2];
    const float* W_c   = (const float*)d_in[3];
    const float* b_c   = (const float*)d_in[4];
    const float* Wq    = (const float*)d_in[5];
    const float* bq    = (const float*)d_in[6];
    const float* Wk    = (const float*)d_in[7];
    const float* bk    = (const float*)d_in[8];
    const float* Wv    = (const float*)d_in[9];
    const float* bv    = (const float*)d_in[10];
    const float* W1    = (const float*)d_in[11];
    const float* b1    = (const float*)d_in[12];
    const float* W2    = (const float*)d_in[13];
    const float* b2    = (const float*)d_in[14];
    const float* W3    = (const float*)d_in[15];
    const float* b3    = (const float*)d_in[16];

    size_t smemA = SMEM_A_FLOATS * sizeof(float);
    size_t smemB = SMEM_B_FLOATS * sizeof(float);
    cudaFuncSetAttribute(kernelA, cudaFuncAttributeMaxDynamicSharedMemorySize, (int)smemA);
    cudaFuncSetAttribute(kernelB, cudaFuncAttributeMaxDynamicSharedMemorySize, (int)smemB);

    kernelA<<<152, 256, smemA>>>(x, W_in, b_in, W_c, b_c, Wq, bq, Wk, bk, Wv, bv);
    kernelB<<<152, 256, smemB>>>(W1, b1, W2, b2, W3, b3, (float*)d_out);
}

// round 6
// speedup vs baseline: 5.2335x; 5.2335x over previous
#include <cuda_runtime.h>
#include <cuda_bf16.h>
#include <cstdint>

#define T 48
#define E 32
#define C0 64
#define C1 64
#define H1 256
#define H2 128
#define NPRED 12
#define SEQS (16 * 2048)

__device__ float g_last[SEQS * C1];

// ---- kernel A smem byte offsets ----
#define O_WIN_H 0        // WinT [64n][40k] bf16 (k<32 valid), stride 80B
#define O_WIN_L 5120
#define O_WC_H  10240    // WcT 3 x [64n][72k] bf16, stride 144B, dt stride 9216
#define O_WC_L  37888
#define O_WK_H  65536    // WkT [64][72]
#define O_WK_L  74752
#define O_WV_H  83968
#define O_WV_L  93184
#define O_WQ    102400   // Wq fp32 [64][64]
#define O_X_H   118784   // x [96r][40k] bf16, stride 80B
#define O_X_L   126464
#define O_H_H   134144   // h padded [2][50][72] bf16, row stride 144B, seq stride 7200
#define O_H_L   148544
#define O_HC_H  162944   // hc [96][72] bf16, stride 144B
#define O_HC_L  176768
#define O_LAST  190592   // fp32 [2][64]
#define O_SQ    191104   // fp32 [2][64]
#define O_PART  191632   // fp32 [8w][96r]
#define O_ATTN  194704   // fp32 [2][48]
#define O_BIAS  195216   // fp32: bin@0 bc@64 bk@128 bv@192 bq@256
#define SMEM_A  196496

// ---------------- warp MMA helpers (portable PTX, plain sm_103 OK) ----------------
__device__ __forceinline__ uint32_t smem_u32(const void* p) {
    uint32_t a;
    asm("{ .reg .u64 t; cvta.to.shared.u64 t, %1; cvt.u32.u64 %0, t; }" : "=r"(a) : "l"(p));
    return a;
}
__device__ __forceinline__ void hmma(float* d, const uint32_t* a, const uint32_t* b) {
    asm volatile(
        "mma.sync.aligned.m16n8k16.row.col.f32.bf16.bf16.f32 "
        "{%0,%1,%2,%3}, {%4,%5,%6,%7}, {%8,%9}, {%0,%1,%2,%3};"
        : "+f"(d[0]), "+f"(d[1]), "+f"(d[2]), "+f"(d[3])
        : "r"(a[0]), "r"(a[1]), "r"(a[2]), "r"(a[3]), "r"(b[0]), "r"(b[1]));
}
// A 16x16 frag from [row][k] bf16 storage; rowbase = base + m0*stride
__device__ __forceinline__ void ldA(uint32_t* f, uint32_t rowbase, int stride, int k0, int lane) {
    int g = lane >> 3;
    uint32_t addr = rowbase + (uint32_t)(((lane & 7) + ((g & 1) << 3)) * stride
                                         + (k0 + ((g >> 1) << 3)) * 2);
    asm volatile("ldmatrix.sync.aligned.m8n8.x4.shared.b16 {%0,%1,%2,%3}, [%4];"
                 : "=r"(f[0]), "=r"(f[1]), "=r"(f[2]), "=r"(f[3]) : "r"(addr));
}
// B 16k x 8n frag from [n][k] bf16 storage
__device__ __forceinline__ void ldB(uint32_t* f, uint32_t base, int stride, int cb, int k0, int lane) {
    uint32_t addr = base + (uint32_t)((cb + (lane & 7)) * stride + k0 * 2
                                      + (((lane >> 3) & 1) << 4));
    asm volatile("ldmatrix.sync.aligned.m8n8.x2.shared.b16 {%0,%1}, [%2];"
                 : "=r"(f[0]), "=r"(f[1]) : "r"(addr));
}
__device__ __forceinline__ void splitw(float a, float b, uint32_t& hw, uint32_t& lw) {
    __nv_bfloat162 H = __floats2bfloat162_rn(a, b);
    float2 F = __bfloat1622float2(H);
    __nv_bfloat162 L = __floats2bfloat162_rn(a - F.x, b - F.y);
    hw = *reinterpret_cast<uint32_t*>(&H);
    lw = *reinterpret_cast<uint32_t*>(&L);
}

// ---------------- Kernel A: HMMA split-bf16 GEMMs + exact fp32 attention ----------------
__global__ void __launch_bounds__(256, 1)
kernelA(const float* __restrict__ x,
        const float* __restrict__ Win, const float* __restrict__ bin,
        const float* __restrict__ Wc,  const float* __restrict__ bc,
        const float* __restrict__ Wq,  const float* __restrict__ bq,
        const float* __restrict__ Wk,  const float* __restrict__ bk,
        const float* __restrict__ Wv,  const float* __restrict__ bv)
{
    extern __shared__ char smc[];
    const uint32_t smb = smem_u32(smc);
    const int tid  = threadIdx.x;
    const int wid  = tid >> 5;
    const int lane = tid & 31;
    const int cb   = wid * 8;                  // this warp's output col base

    float* sBias = (float*)(smc + O_BIAS);
    float* sLast = (float*)(smc + O_LAST);
    float* sQ    = (float*)(smc + O_SQ);
    float* sPart = (float*)(smc + O_PART);
    float* sAttn = (float*)(smc + O_ATTN);

    // ---- stage weights: transpose to [n][k], split hi/lo bf16 ----
    for (int i = tid; i < 2048; i += 256) {          // Win[e][c] -> WinT[c][e]
        int e = i >> 6, c = i & 63;
        float w = Win[i];
        __nv_bfloat16 h = __float2bfloat16(w);
        *(__nv_bfloat16*)(smc + O_WIN_H + c * 80 + e * 2) = h;
        *(__nv_bfloat16*)(smc + O_WIN_L + c * 80 + e * 2) =
            __float2bfloat16(w - __bfloat162float(h));
    }
    for (int i = tid; i < 12288; i += 256) {         // Wc[dt][ci][co] -> [dt][co][ci]
        int dt = i >> 12, r = i & 4095, ci = r >> 6, co = r & 63;
        float w = Wc[i];
        __nv_bfloat16 h = __float2bfloat16(w);
        uint32_t o = dt * 9216 + co * 144 + ci * 2;
        *(__nv_bfloat16*)(smc + O_WC_H + o) = h;
        *(__nv_bfloat16*)(smc + O_WC_L + o) = __float2bfloat16(w - __bfloat162float(h));
    }
    for (int i = tid; i < 4096; i += 256) {          // Wk/Wv[ci][co] -> [co][ci]; Wq fp32
        int ci = i >> 6, co = i & 63;
        uint32_t o = co * 144 + ci * 2;
        float wk = Wk[i];
        __nv_bfloat16 h = __float2bfloat16(wk);
        *(__nv_bfloat16*)(smc + O_WK_H + o) = h;
        *(__nv_bfloat16*)(smc + O_WK_L + o) = __float2bfloat16(wk - __bfloat162float(h));
        float wv = Wv[i];
        __nv_bfloat16 hv = __float2bfloat16(wv);
        *(__nv_bfloat16*)(smc + O_WV_H + o) = hv;
        *(__nv_bfloat16*)(smc + O_WV_L + o) = __float2bfloat16(wv - __bfloat162float(hv));
        ((float*)(smc + O_WQ))[i] = Wq[i];
    }
    if (tid < 64) {
        sBias[tid]       = bin[tid];
        sBias[64 + tid]  = bc[tid];
        sBias[128 + tid] = bk[tid];
        sBias[192 + tid] = bv[tid];
        sBias[256 + tid] = bq[tid];
    }
    // zero padded-h region (rows 0/49 of each seq stay zero forever)
    for (int i = tid; i < 7200; i += 256) ((uint32_t*)(smc + O_H_H))[i] = 0;
    __syncthreads();

    for (int pair = blockIdx.x; pair < SEQS / 2; pair += gridDim.x) {
        const int seq0 = pair * 2;

        // ---- stage x: 2 seqs, [96r][32k] split hi/lo, stride 80B ----
        {
            const float4* xg = (const float4*)(x + (size_t)seq0 * (T * E));
            #pragma unroll
            for (int kk = 0; kk < 3; kk++) {
                int idx = tid + kk * 256;            // 0..767
                float4 v = xg[idx];
                int row = idx >> 3, e4 = idx & 7;
                uint32_t o = (uint32_t)(row * 80 + e4 * 8);
                uint32_t h0, l0, h1, l1;
                splitw(v.x, v.y, h0, l0);
                splitw(v.z, v.w, h1, l1);
                *(uint32_t*)(smc + O_X_H + o)     = h0;
                *(uint32_t*)(smc + O_X_H + o + 4) = h1;
                *(uint32_t*)(smc + O_X_L + o)     = l0;
                *(uint32_t*)(smc + O_X_L + o + 4) = l1;
            }
        }
        __syncthreads();

        // ---- GEMM1: h = x @ Win (K=32) ----
        {
            float acc[6][4] = {};
            #pragma unroll
            for (int k = 0; k < 2; k++) {
                int k0 = k * 16;
                uint32_t bh[2], bl[2];
                ldB(bh, smb + O_WIN_H, 80, cb, k0, lane);
                ldB(bl, smb + O_WIN_L, 80, cb, k0, lane);
                #pragma unroll
                for (int mt = 0; mt < 6; mt++) {
                    uint32_t ah[4], al[4];
                    ldA(ah, smb + O_X_H + mt * 16 * 80, 80, k0, lane);
                    ldA(al, smb + O_X_L + mt * 16 * 80, 80, k0, lane);
                    hmma(acc[mt], ah, bh);
                    hmma(acc[mt], ah, bl);
                    hmma(acc[mt], al, bh);
                }
            }
            // ep1: + bin, store bf16 hi/lo into padded h
            int c = cb + (lane & 3) * 2;
            float b0 = sBias[c], b1 = sBias[c + 1];
            #pragma unroll
            for (int mt = 0; mt < 6; mt++) {
                int g0 = mt * 16 + (lane >> 2), g1 = g0 + 8;
                uint32_t h0, l0, h1, l1;
                splitw(acc[mt][0] + b0, acc[mt][1] + b1, h0, l0);
                splitw(acc[mt][2] + b0, acc[mt][3] + b1, h1, l1);
                int s0 = g0 / 48, t0 = g0 % 48;
                int s1 = g1 / 48, t1 = g1 % 48;
                uint32_t o0 = (uint32_t)(s0 * 7200 + (t0 + 1) * 144 + c * 2);
                uint32_t o1 = (uint32_t)(s1 * 7200 + (t1 + 1) * 144 + c * 2);
                *(uint32_t*)(smc + O_H_H + o0) = h0;
                *(uint32_t*)(smc + O_H_L + o0) = l0;
                *(uint32_t*)(smc + O_H_H + o1) = h1;
                *(uint32_t*)(smc + O_H_L + o1) = l1;
            }
        }
        __syncthreads();

        // ---- GEMM2: hc = relu(conv(h)) : 3 accumulated K=64 GEMMs ----
        {
            float acc[6][4] = {};
            #pragma unroll
            for (int dt = 0; dt < 3; dt++) {
                #pragma unroll
                for (int k = 0; k < 4; k++) {
                    int k0 = k * 16;
                    uint32_t bh[2], bl[2];
                    ldB(bh, smb + O_WC_H + dt * 9216, 144, cb, k0, lane);
                    ldB(bl, smb + O_WC_L + dt * 9216, 144, cb, k0, lane);
                    #pragma unroll
                    for (int mt = 0; mt < 6; mt++) {
                        int sq = (mt >= 3), t0 = (mt - sq * 3) * 16;
                        uint32_t rb = (uint32_t)(sq * 7200 + (t0 + dt) * 144);
                        uint32_t ah[4], al[4];
                        ldA(ah, smb + O_H_H + rb, 144, k0, lane);
                        ldA(al, smb + O_H_L + rb, 144, k0, lane);
                        hmma(acc[mt], ah, bh);
                        hmma(acc[mt], ah, bl);
                        hmma(acc[mt], al, bh);
                    }
                }
            }
            // ep2: relu(+bc), store hc hi/lo; save t==47 rows fp32
            int c = cb + (lane & 3) * 2;
            float b0 = sBias[64 + c], b1 = sBias[64 + c + 1];
            #pragma unroll
            for (int mt = 0; mt < 6; mt++) {
                int g0 = mt * 16 + (lane >> 2), g1 = g0 + 8;
                float v0 = fmaxf(acc[mt][0] + b0, 0.f), v1 = fmaxf(acc[mt][1] + b1, 0.f);
                float v2 = fmaxf(acc[mt][2] + b0, 0.f), v3 = fmaxf(acc[mt][3] + b1, 0.f);
                uint32_t h0, l0, h1, l1;
                splitw(v0, v1, h0, l0);
                splitw(v2, v3, h1, l1);
                uint32_t o0 = (uint32_t)(g0 * 144 + c * 2);
                uint32_t o1 = (uint32_t)(g1 * 144 + c * 2);
                *(uint32_t*)(smc + O_HC_H + o0) = h0;
                *(uint32_t*)(smc + O_HC_L + o0) = l0;
                *(uint32_t*)(smc + O_HC_H + o1) = h1;
                *(uint32_t*)(smc + O_HC_L + o1) = l1;
                if ((g1 % 48) == 47) {               // rows 47 / 95
                    int s = g1 / 48;
                    sLast[s * 64 + c]     = v2;
                    sLast[s * 64 + c + 1] = v3;
                }
            }
        }
        __syncthreads();

        // ---- q = bq + hc_last @ Wq (exact fp32) ----
        if (tid < 128) {
            int s = tid >> 6, c = tid & 63;
            const float* wq = (float*)(smc + O_WQ);
            const float* hl = sLast + s * 64;
            float a = sBias[256 + c];
            #pragma unroll 8
            for (int ci = 0; ci < 64; ci++) a += hl[ci] * wq[ci * 64 + c];
            sQ[s * 64 + c] = a;
        }
        __syncthreads();

        // ---- GEMM3: k = hc @ Wk ; score partials straight from fragments ----
        {
            float acc[6][4] = {};
            #pragma unroll
            for (int k = 0; k < 4; k++) {
                int k0 = k * 16;
                uint32_t bh[2], bl[2];
                ldB(bh, smb + O_WK_H, 144, cb, k0, lane);
                ldB(bl, smb + O_WK_L, 144, cb, k0, lane);
                #pragma unroll
                for (int mt = 0; mt < 6; mt++) {
                    uint32_t ah[4], al[4];
                    ldA(ah, smb + O_HC_H + mt * 16 * 144, 144, k0, lane);
                    ldA(al, smb + O_HC_L + mt * 16 * 144, 144, k0, lane);
                    hmma(acc[mt], ah, bh);
                    hmma(acc[mt], ah, bl);
                    hmma(acc[mt], al, bh);
                }
            }
            int c = cb + (lane & 3) * 2;
            #pragma unroll
            for (int mt = 0; mt < 6; mt++) {
                const float* q = sQ + ((mt >= 3) ? 64 : 0);
                float q0 = q[c], q1 = q[c + 1];
                float p0 = q0 * acc[mt][0] + q1 * acc[mt][1];
                float p1 = q0 * acc[mt][2] + q1 * acc[mt][3];
                p0 += __shfl_xor_sync(0xffffffffu, p0, 1);
                p0 += __shfl_xor_sync(0xffffffffu, p0, 2);
                p1 += __shfl_xor_sync(0xffffffffu, p1, 1);
                p1 += __shfl_xor_sync(0xffffffffu, p1, 2);
                if ((lane & 3) == 0) {
                    int g0 = mt * 16 + (lane >> 2);
                    sPart[wid * 96 + g0]     = p0;
                    sPart[wid * 96 + g0 + 8] = p1;
                }
            }
        }
        __syncthreads();

        // ---- softmax over 48 (warp s), scores = (q.k + q.bk)/8 ----
        if (wid < 2) {
            const float* q = sQ + wid * 64;
            const float* kb = sBias + 128;
            float qb = q[lane] * kb[lane] + q[lane + 32] * kb[lane + 32];
            #pragma unroll
            for (int o = 16; o > 0; o >>= 1) qb += __shfl_xor_sync(0xffffffffu, qb, o);
            int base = wid * 48;
            float a = 0.f, b2 = 0.f;
            #pragma unroll
            for (int w = 0; w < 8; w++) a += sPart[w * 96 + base + lane];
            if (lane < 16) {
                #pragma unroll
                for (int w = 0; w < 8; w++) b2 += sPart[w * 96 + base + 32 + lane];
            }
            a  = (a + qb) * 0.125f;
            b2 = (lane < 16) ? (b2 + qb) * 0.125f : -1e30f;
            float m = fmaxf(a, b2);
            #pragma unroll
            for (int o = 16; o > 0; o >>= 1) m = fmaxf(m, __shfl_xor_sync(0xffffffffu, m, o));
            float ea = __expf(a - m);
            float eb = (lane < 16) ? __expf(b2 - m) : 0.f;
            float s = ea + eb;
            #pragma unroll
            for (int o = 16; o > 0; o >>= 1) s += __shfl_xor_sync(0xffffffffu, s, o);
            float inv = 1.f / s;
            sAttn[base + lane] = ea * inv;
            if (lane < 16) sAttn[base + 32 + lane] = eb * inv;
        }
        __syncthreads();

        // ---- GEMM4: v = hc @ Wv ; ctx = attn.v straight from fragments ----
        {
            float acc[6][4] = {};
            #pragma unroll
            for (int k = 0; k < 4; k++) {
                int k0 = k * 16;
                uint32_t bh[2], bl[2];
                ldB(bh, smb + O_WV_H, 144, cb, k0, lane);
                ldB(bl, smb + O_WV_L, 144, cb, k0, lane);
                #pragma unroll
                for (int mt = 0; mt < 6; mt++) {
                    uint32_t ah[4], al[4];
                    ldA(ah, smb + O_HC_H + mt * 16 * 144, 144, k0, lane);
                    ldA(al, smb + O_HC_L + mt * 16 * 144, 144, k0, lane);
                    hmma(acc[mt], ah, bh);
                    hmma(acc[mt], ah, bl);
                    hmma(acc[mt], al, bh);
                }
            }
            int c = cb + (lane & 3) * 2;
            #pragma unroll
            for (int sq = 0; sq < 2; sq++) {
                float c0 = 0.f, c1 = 0.f;
                #pragma unroll
                for (int mt3 = 0; mt3 < 3; mt3++) {
                    int mt = sq * 3 + mt3;
                    int t0 = mt3 * 16 + (lane >> 2), t1 = t0 + 8;
                    float a0 = sAttn[sq * 48 + t0], a1 = sAttn[sq * 48 + t1];
                    c0 += a0 * acc[mt][0] + a1 * acc[mt][2];
                    c1 += a0 * acc[mt][1] + a1 * acc[mt][3];
                }
                #pragma unroll
                for (int o = 4; o < 32; o <<= 1) {
                    c0 += __shfl_xor_sync(0xffffffffu, c0, o);
                    c1 += __shfl_xor_sync(0xffffffffu, c1, o);
                }
                if ((lane >> 2) == 0) {
                    g_last[(size_t)(seq0 + sq) * 64 + c]     = c0 + sBias[192 + c];
                    g_last[(size_t)(seq0 + sq) * 64 + c + 1] = c1 + sBias[192 + c + 1];
                }
            }
        }
        __syncthreads();
    }
}

// ---------------- Kernel B: MLP 64 -> 256 -> 128 -> 12 (proven round-1 version) ----------------
#define SMEM_B_FLOATS 54672

__global__ void __launch_bounds__(256, 1)
kernelB(const float* __restrict__ W1, const float* __restrict__ b1,
        const float* __restrict__ W2, const float* __restrict__ b2,
        const float* __restrict__ W3, const float* __restrict__ b3,
        float* __restrict__ out)
{
    extern __shared__ float sm[];
    float* sW1 = sm;
    float* sW2 = sm + 16384;
    float* sW3 = sm + 49152;
    float* sb1 = sm + 50688;
    float* sb2 = sm + 50944;
    float* sb3 = sm + 51072;
    float* sIn = sm + 51088;
    float* sZ1 = sm + 51600;
    float* sZ2 = sm + 53648;

    const int tid = threadIdx.x;

    for (int i = tid; i < 16384; i += 256) sW1[i] = W1[i];
    for (int i = tid; i < 32768; i += 256) sW2[i] = W2[i];
    for (int i = tid; i < 1536; i += 256) sW3[i] = W3[i];
    if (tid < 256) sb1[tid] = b1[tid];
    if (tid < 128) sb2[tid] = b2[tid];
    if (tid < 12)  sb3[tid] = b3[tid];
    __syncthreads();

    for (int base = blockIdx.x * 8; base < SEQS; base += gridDim.x * 8) {
        {
            const float4* src = (const float4*)(g_last + (size_t)base * C1);
            float4* dst = (float4*)sIn;
            for (int i = tid; i < 128; i += 256) dst[i] = src[i];
        }
        __syncthreads();

        {
            int c64 = tid & 63, rr = tid >> 6;
            float4 bb = ((const float4*)sb1)[c64];
            float a0[4] = {bb.x, bb.y, bb.z, bb.w};
            float a1[4] = {bb.x, bb.y, bb.z, bb.w};
            #pragma unroll 8
            for (int f = 0; f < 64; f++) {
                float4 w = ((const float4*)(sW1 + f * H1))[c64];
                float x0 = sIn[rr * 64 + f];
                float x1 = sIn[(rr + 4) * 64 + f];
                a0[0] += x0 * w.x; a0[1] += x0 * w.y; a0[2] += x0 * w.z; a0[3] += x0 * w.w;
                a1[0] += x1 * w.x; a1[1] += x1 * w.y; a1[2] += x1 * w.z; a1[3] += x1 * w.w;
            }
            ((float4*)(sZ1 + rr * H1))[c64] =
                make_float4(fmaxf(a0[0], 0.f), fmaxf(a0[1], 0.f), fmaxf(a0[2], 0.f), fmaxf(a0[3], 0.f));
            ((float4*)(sZ1 + (rr + 4) * H1))[c64] =
                make_float4(fmaxf(a1[0], 0.f), fmaxf(a1[1], 0.f), fmaxf(a1[2], 0.f), fmaxf(a1[3], 0.f));
        }
        __syncthreads();

        {
            int c32 = tid & 31, r = tid >> 5;
            float4 bb = ((const float4*)sb2)[c32];
            float a[4] = {bb.x, bb.y, bb.z, bb.w};
            #pragma unroll 8
            for (int f = 0; f < 256; f++) {
                float4 w = ((const float4*)(sW2 + f * H2))[c32];
                float z = sZ1[r * H1 + f];
                a[0] += z * w.x; a[1] += z * w.y; a[2] += z * w.z; a[3] += z * w.w;
            }
            ((float4*)(sZ2 + r * H2))[c32] =
                make_float4(fmaxf(a[0], 0.f), fmaxf(a[1], 0.f), fmaxf(a[2], 0.f), fmaxf(a[3], 0.f));
        }
        __syncthreads();

        if (tid < 96) {
            int r = tid / 12, p = tid % 12;
            float a = sb3[p];
            #pragma unroll 16
            for (int f = 0; f < 128; f++) a += sZ2[r * H2 + f] * sW3[f * NPRED + p];
            int seqr = base + r;
            int bb = seqr >> 11;
            int nn = seqr & 2047;
            out[(size_t)bb * (NPRED * 2048) + p * 2048 + nn] = a;
        }
        __syncthreads();
    }
}

extern "C" void kernel_launch(void* const* d_in, const int* in_sizes, int n_in,
                              void* d_out, int out_size)
{
    const float* x     = (const float*)d_in[0];
    const float* W_in  = (const float*)d_in[1];
    const float* b_in  = (const float*)d_in[2];
    const float* W_c   = (const float*)d_in[3];
    const float* b_c   = (const float*)d_in[4];
    const float* Wq    = (const float*)d_in[5];
    const float* bq    = (const float*)d_in[6];
    const float* Wk    = (const float*)d_in[7];
    const float* bk    = (const float*)d_in[8];
    const float* Wv    = (const float*)d_in[9];
    const float* bv    = (const float*)d_in[10];
    const float* W1    = (const float*)d_in[11];
    const float* b1    = (const float*)d_in[12];
    const float* W2    = (const float*)d_in[13];
    const float* b2    = (const float*)d_in[14];
    const float* W3    = (const float*)d_in[15];
    const float* b3    = (const float*)d_in[16];

    size_t smemB = SMEM_B_FLOATS * sizeof(float);
    cudaFuncSetAttribute(kernelA, cudaFuncAttributeMaxDynamicSharedMemorySize, SMEM_A);
    cudaFuncSetAttribute(kernelB, cudaFuncAttributeMaxDynamicSharedMemorySize, (int)smemB);

    kernelA<<<152, 256, SMEM_A>>>(x, W_in, b_in, W_c, b_c, Wq, bq, Wk, bk, Wv, bv);
    kernelB<<<152, 256, smemB>>>(W1, b1, W2, b2, W3, b3, (float*)d_out);
}

// round 7
// speedup vs baseline: 6.0282x; 1.1518x over previous
#include <cuda_runtime.h>
#include <cuda_bf16.h>
#include <cstdint>

#define T 48
#define E 32
#define C0 64
#define C1 64
#define H1 256
#define H2 128
#define NPRED 12
#define SEQS (16 * 2048)

__device__ float g_last[SEQS * C1];

// ---- kernel A smem byte offsets ----
#define O_WIN_H 0        // WinT [64n][40k] bf16 (k<32 valid), stride 80B
#define O_WIN_L 5120
#define O_WC_H  10240    // WcT 3 x [64n][72k] bf16, stride 144B, dt stride 9216
#define O_WC_L  37888
#define O_WK_H  65536    // WkT [64][72]
#define O_WK_L  74752
#define O_WV_H  83968
#define O_WV_L  93184
#define O_WQ    102400   // Wq fp32 [64][64]
#define O_X_H   118784   // x [96r][40k] bf16, stride 80B
#define O_X_L   126464
#define O_H_H   134144   // h padded [2][50][72] bf16, row stride 144B, seq stride 7200
#define O_H_L   148544
#define O_HC_H  162944   // hc [96][72] bf16, stride 144B
#define O_HC_L  176768
#define O_LAST  190592   // fp32 [2][64]
#define O_SQ    191104   // fp32 [2][64]
#define O_PART  191632   // fp32 [8w][96r]
#define O_ATTN  194704   // fp32 [2][48]
#define O_BIAS  195216   // fp32: bin@0 bc@64 bk@128 bv@192 bq@256
#define SMEM_A  196496

// ---------------- warp MMA helpers (portable PTX, plain sm_103 OK) ----------------
__device__ __forceinline__ uint32_t smem_u32(const void* p) {
    uint32_t a;
    asm("{ .reg .u64 t; cvta.to.shared.u64 t, %1; cvt.u32.u64 %0, t; }" : "=r"(a) : "l"(p));
    return a;
}
__device__ __forceinline__ void hmma(float* d, const uint32_t* a, const uint32_t* b) {
    asm volatile(
        "mma.sync.aligned.m16n8k16.row.col.f32.bf16.bf16.f32 "
        "{%0,%1,%2,%3}, {%4,%5,%6,%7}, {%8,%9}, {%0,%1,%2,%3};"
        : "+f"(d[0]), "+f"(d[1]), "+f"(d[2]), "+f"(d[3])
        : "r"(a[0]), "r"(a[1]), "r"(a[2]), "r"(a[3]), "r"(b[0]), "r"(b[1]));
}
__device__ __forceinline__ void ldA(uint32_t* f, uint32_t rowbase, int stride, int k0, int lane) {
    int g = lane >> 3;
    uint32_t addr = rowbase + (uint32_t)(((lane & 7) + ((g & 1) << 3)) * stride
                                         + (k0 + ((g >> 1) << 3)) * 2);
    asm volatile("ldmatrix.sync.aligned.m8n8.x4.shared.b16 {%0,%1,%2,%3}, [%4];"
                 : "=r"(f[0]), "=r"(f[1]), "=r"(f[2]), "=r"(f[3]) : "r"(addr));
}
__device__ __forceinline__ void ldB(uint32_t* f, uint32_t base, int stride, int cb, int k0, int lane) {
    uint32_t addr = base + (uint32_t)((cb + (lane & 7)) * stride + k0 * 2
                                      + (((lane >> 3) & 1) << 4));
    asm volatile("ldmatrix.sync.aligned.m8n8.x2.shared.b16 {%0,%1}, [%2];"
                 : "=r"(f[0]), "=r"(f[1]) : "r"(addr));
}
__device__ __forceinline__ void splitw(float a, float b, uint32_t& hw, uint32_t& lw) {
    __nv_bfloat162 H = __floats2bfloat162_rn(a, b);
    float2 F = __bfloat1622float2(H);
    __nv_bfloat162 L = __floats2bfloat162_rn(a - F.x, b - F.y);
    hw = *reinterpret_cast<uint32_t*>(&H);
    lw = *reinterpret_cast<uint32_t*>(&L);
}

// ---------------- Kernel A: HMMA split-bf16 GEMMs + exact fp32 attention ----------------
__global__ void __launch_bounds__(256, 1)
kernelA(const float* __restrict__ x,
        const float* __restrict__ Win, const float* __restrict__ bin,
        const float* __restrict__ Wc,  const float* __restrict__ bc,
        const float* __restrict__ Wq,  const float* __restrict__ bq,
        const float* __restrict__ Wk,  const float* __restrict__ bk,
        const float* __restrict__ Wv,  const float* __restrict__ bv)
{
    extern __shared__ char smc[];
    const uint32_t smb = smem_u32(smc);
    const int tid  = threadIdx.x;
    const int wid  = tid >> 5;
    const int lane = tid & 31;
    const int cb   = wid * 8;

    float* sBias = (float*)(smc + O_BIAS);
    float* sLast = (float*)(smc + O_LAST);
    float* sQ    = (float*)(smc + O_SQ);
    float* sPart = (float*)(smc + O_PART);
    float* sAttn = (float*)(smc + O_ATTN);

    // ---- stage weights ----
    for (int i = tid; i < 2048; i += 256) {
        int e = i >> 6, c = i & 63;
        float w = Win[i];
        __nv_bfloat16 h = __float2bfloat16(w);
        *(__nv_bfloat16*)(smc + O_WIN_H + c * 80 + e * 2) = h;
        *(__nv_bfloat16*)(smc + O_WIN_L + c * 80 + e * 2) =
            __float2bfloat16(w - __bfloat162float(h));
    }
    for (int i = tid; i < 12288; i += 256) {
        int dt = i >> 12, r = i & 4095, ci = r >> 6, co = r & 63;
        float w = Wc[i];
        __nv_bfloat16 h = __float2bfloat16(w);
        uint32_t o = dt * 9216 + co * 144 + ci * 2;
        *(__nv_bfloat16*)(smc + O_WC_H + o) = h;
        *(__nv_bfloat16*)(smc + O_WC_L + o) = __float2bfloat16(w - __bfloat162float(h));
    }
    for (int i = tid; i < 4096; i += 256) {
        int ci = i >> 6, co = i & 63;
        uint32_t o = co * 144 + ci * 2;
        float wk = Wk[i];
        __nv_bfloat16 h = __float2bfloat16(wk);
        *(__nv_bfloat16*)(smc + O_WK_H + o) = h;
        *(__nv_bfloat16*)(smc + O_WK_L + o) = __float2bfloat16(wk - __bfloat162float(h));
        float wv = Wv[i];
        __nv_bfloat16 hv = __float2bfloat16(wv);
        *(__nv_bfloat16*)(smc + O_WV_H + o) = hv;
        *(__nv_bfloat16*)(smc + O_WV_L + o) = __float2bfloat16(wv - __bfloat162float(hv));
        ((float*)(smc + O_WQ))[i] = Wq[i];
    }
    if (tid < 64) {
        sBias[tid]       = bin[tid];
        sBias[64 + tid]  = bc[tid];
        sBias[128 + tid] = bk[tid];
        sBias[192 + tid] = bv[tid];
        sBias[256 + tid] = bq[tid];
    }
    for (int i = tid; i < 7200; i += 256) ((uint32_t*)(smc + O_H_H))[i] = 0;
    __syncthreads();

    // ---- prologue: stage x for first pair ----
    {
        const float4* xg = (const float4*)(x + (size_t)(blockIdx.x * 2) * (T * E));
        #pragma unroll
        for (int kk = 0; kk < 3; kk++) {
            int idx = tid + kk * 256;
            float4 v = xg[idx];
            int row = idx >> 3, e4 = idx & 7;
            uint32_t o = (uint32_t)(row * 80 + e4 * 8);
            uint32_t h0, l0, h1, l1;
            splitw(v.x, v.y, h0, l0);
            splitw(v.z, v.w, h1, l1);
            *(uint32_t*)(smc + O_X_H + o)     = h0;
            *(uint32_t*)(smc + O_X_H + o + 4) = h1;
            *(uint32_t*)(smc + O_X_L + o)     = l0;
            *(uint32_t*)(smc + O_X_L + o + 4) = l1;
        }
    }
    __syncthreads();

    for (int pair = blockIdx.x; pair < SEQS / 2; pair += gridDim.x) {
        const int seq0 = pair * 2;

        // ---- GEMM1: h = x @ Win (K=32) ----
        {
            float acc[6][4] = {};
            #pragma unroll
            for (int k = 0; k < 2; k++) {
                int k0 = k * 16;
                uint32_t bh[2], bl[2];
                ldB(bh, smb + O_WIN_H, 80, cb, k0, lane);
                ldB(bl, smb + O_WIN_L, 80, cb, k0, lane);
                #pragma unroll
                for (int mt = 0; mt < 6; mt++) {
                    uint32_t ah[4], al[4];
                    ldA(ah, smb + O_X_H + mt * 16 * 80, 80, k0, lane);
                    ldA(al, smb + O_X_L + mt * 16 * 80, 80, k0, lane);
                    hmma(acc[mt], ah, bh);
                    hmma(acc[mt], ah, bl);
                    hmma(acc[mt], al, bh);
                }
            }
            int c = cb + (lane & 3) * 2;
            float b0 = sBias[c], b1 = sBias[c + 1];
            #pragma unroll
            for (int mt = 0; mt < 6; mt++) {
                int g0 = mt * 16 + (lane >> 2), g1 = g0 + 8;
                uint32_t h0, l0, h1, l1;
                splitw(acc[mt][0] + b0, acc[mt][1] + b1, h0, l0);
                splitw(acc[mt][2] + b0, acc[mt][3] + b1, h1, l1);
                int s0 = g0 / 48, t0 = g0 % 48;
                int s1 = g1 / 48, t1 = g1 % 48;
                uint32_t o0 = (uint32_t)(s0 * 7200 + (t0 + 1) * 144 + c * 2);
                uint32_t o1 = (uint32_t)(s1 * 7200 + (t1 + 1) * 144 + c * 2);
                *(uint32_t*)(smc + O_H_H + o0) = h0;
                *(uint32_t*)(smc + O_H_L + o0) = l0;
                *(uint32_t*)(smc + O_H_H + o1) = h1;
                *(uint32_t*)(smc + O_H_L + o1) = l1;
            }
        }
        __syncthreads();

        // ---- prefetch next pair's x into registers (latency hidden by GEMMs) ----
        const int npair = pair + gridDim.x;
        const bool hasnext = npair < SEQS / 2;
        float4 nx0, nx1, nx2;
        if (hasnext) {
            const float4* xg = (const float4*)(x + (size_t)(npair * 2) * (T * E));
            nx0 = xg[tid];
            nx1 = xg[tid + 256];
            nx2 = xg[tid + 512];
        }

        // ---- GEMM2: hc = relu(conv(h)) ----
        {
            float acc[6][4] = {};
            #pragma unroll
            for (int dt = 0; dt < 3; dt++) {
                #pragma unroll
                for (int k = 0; k < 4; k++) {
                    int k0 = k * 16;
                    uint32_t bh[2], bl[2];
                    ldB(bh, smb + O_WC_H + dt * 9216, 144, cb, k0, lane);
                    ldB(bl, smb + O_WC_L + dt * 9216, 144, cb, k0, lane);
                    #pragma unroll
                    for (int mt = 0; mt < 6; mt++) {
                        int sq = (mt >= 3), t0 = (mt - sq * 3) * 16;
                        uint32_t rb = (uint32_t)(sq * 7200 + (t0 + dt) * 144);
                        uint32_t ah[4], al[4];
                        ldA(ah, smb + O_H_H + rb, 144, k0, lane);
                        ldA(al, smb + O_H_L + rb, 144, k0, lane);
                        hmma(acc[mt], ah, bh);
                        hmma(acc[mt], ah, bl);
                        hmma(acc[mt], al, bh);
                    }
                }
            }
            int c = cb + (lane & 3) * 2;
            float b0 = sBias[64 + c], b1 = sBias[64 + c + 1];
            #pragma unroll
            for (int mt = 0; mt < 6; mt++) {
                int g0 = mt * 16 + (lane >> 2), g1 = g0 + 8;
                float v0 = fmaxf(acc[mt][0] + b0, 0.f), v1 = fmaxf(acc[mt][1] + b1, 0.f);
                float v2 = fmaxf(acc[mt][2] + b0, 0.f), v3 = fmaxf(acc[mt][3] + b1, 0.f);
                uint32_t h0, l0, h1, l1;
                splitw(v0, v1, h0, l0);
                splitw(v2, v3, h1, l1);
                uint32_t o0 = (uint32_t)(g0 * 144 + c * 2);
                uint32_t o1 = (uint32_t)(g1 * 144 + c * 2);
                *(uint32_t*)(smc + O_HC_H + o0) = h0;
                *(uint32_t*)(smc + O_HC_L + o0) = l0;
                *(uint32_t*)(smc + O_HC_H + o1) = h1;
                *(uint32_t*)(smc + O_HC_L + o1) = l1;
                if ((g1 % 48) == 47) {
                    int s = g1 / 48;
                    sLast[s * 64 + c]     = v2;
                    sLast[s * 64 + c + 1] = v3;
                }
            }
        }
        __syncthreads();

        // ---- q = bq + hc_last @ Wq (spread over all 256 threads) ----
        {
            int s  = tid >> 7;
            int c  = (tid >> 1) & 63;
            int hh = tid & 1;
            const float* wq = (float*)(smc + O_WQ);
            const float* hl = sLast + s * 64;
            float a = hh ? 0.f : sBias[256 + c];
            int base = hh * 32;
            #pragma unroll 8
            for (int ci = 0; ci < 32; ci++) a += hl[base + ci] * wq[(base + ci) * 64 + c];
            a += __shfl_xor_sync(0xffffffffu, a, 1);
            if (!hh) sQ[s * 64 + c] = a;
        }
        __syncthreads();

        // ---- GEMM3+4 merged: k & v from shared A-fragments ----
        {
            float ack[6][4] = {};
            float acv[6][4] = {};
            #pragma unroll
            for (int k = 0; k < 4; k++) {
                int k0 = k * 16;
                uint32_t bkh[2], bkl[2], bvh[2], bvl[2];
                ldB(bkh, smb + O_WK_H, 144, cb, k0, lane);
                ldB(bkl, smb + O_WK_L, 144, cb, k0, lane);
                ldB(bvh, smb + O_WV_H, 144, cb, k0, lane);
                ldB(bvl, smb + O_WV_L, 144, cb, k0, lane);
                #pragma unroll
                for (int mt = 0; mt < 6; mt++) {
                    uint32_t ah[4], al[4];
                    ldA(ah, smb + O_HC_H + mt * 16 * 144, 144, k0, lane);
                    ldA(al, smb + O_HC_L + mt * 16 * 144, 144, k0, lane);
                    hmma(ack[mt], ah, bkh);
                    hmma(ack[mt], ah, bkl);
                    hmma(ack[mt], al, bkh);
                    hmma(acv[mt], ah, bvh);
                    hmma(acv[mt], ah, bvl);
                    hmma(acv[mt], al, bvh);
                }
            }
            // score partials from ack
            int c = cb + (lane & 3) * 2;
            #pragma unroll
            for (int mt = 0; mt < 6; mt++) {
                const float* q = sQ + ((mt >= 3) ? 64 : 0);
                float q0 = q[c], q1 = q[c + 1];
                float p0 = q0 * ack[mt][0] + q1 * ack[mt][1];
                float p1 = q0 * ack[mt][2] + q1 * ack[mt][3];
                p0 += __shfl_xor_sync(0xffffffffu, p0, 1);
                p0 += __shfl_xor_sync(0xffffffffu, p0, 2);
                p1 += __shfl_xor_sync(0xffffffffu, p1, 1);
                p1 += __shfl_xor_sync(0xffffffffu, p1, 2);
                if ((lane & 3) == 0) {
                    int g0 = mt * 16 + (lane >> 2);
                    sPart[wid * 96 + g0]     = p0;
                    sPart[wid * 96 + g0 + 8] = p1;
                }
            }
            __syncthreads();

            // ---- softmax over 48 (warp s) ----
            if (wid < 2) {
                const float* q = sQ + wid * 64;
                const float* kb = sBias + 128;
                float qb = q[lane] * kb[lane] + q[lane + 32] * kb[lane + 32];
                #pragma unroll
                for (int o = 16; o > 0; o >>= 1) qb += __shfl_xor_sync(0xffffffffu, qb, o);
                int base = wid * 48;
                float a = 0.f, b2 = 0.f;
                #pragma unroll
                for (int w = 0; w < 8; w++) a += sPart[w * 96 + base + lane];
                if (lane < 16) {
                    #pragma unroll
                    for (int w = 0; w < 8; w++) b2 += sPart[w * 96 + base + 32 + lane];
                }
                a  = (a + qb) * 0.125f;
                b2 = (lane < 16) ? (b2 + qb) * 0.125f : -1e30f;
                float m = fmaxf(a, b2);
                #pragma unroll
                for (int o = 16; o > 0; o >>= 1) m = fmaxf(m, __shfl_xor_sync(0xffffffffu, m, o));
                float ea = __expf(a - m);
                float eb = (lane < 16) ? __expf(b2 - m) : 0.f;
                float s = ea + eb;
                #pragma unroll
                for (int o = 16; o > 0; o >>= 1) s += __shfl_xor_sync(0xffffffffu, s, o);
                float inv = 1.f / s;
                sAttn[base + lane] = ea * inv;
                if (lane < 16) sAttn[base + 32 + lane] = eb * inv;
            }
            __syncthreads();

            // ---- ctx = attn . v from retained acv fragments ----
            #pragma unroll
            for (int sq = 0; sq < 2; sq++) {
                float c0 = 0.f, c1 = 0.f;
                #pragma unroll
                for (int mt3 = 0; mt3 < 3; mt3++) {
                    int mt = sq * 3 + mt3;
                    int t0 = mt3 * 16 + (lane >> 2), t1 = t0 + 8;
                    float a0 = sAttn[sq * 48 + t0], a1 = sAttn[sq * 48 + t1];
                    c0 += a0 * acv[mt][0] + a1 * acv[mt][2];
                    c1 += a0 * acv[mt][1] + a1 * acv[mt][3];
                }
                #pragma unroll
                for (int o = 4; o < 32; o <<= 1) {
                    c0 += __shfl_xor_sync(0xffffffffu, c0, o);
                    c1 += __shfl_xor_sync(0xffffffffu, c1, o);
                }
                if ((lane >> 2) == 0) {
                    g_last[(size_t)(seq0 + sq) * 64 + c]     = c0 + sBias[192 + c];
                    g_last[(size_t)(seq0 + sq) * 64 + c + 1] = c1 + sBias[192 + c + 1];
                }
            }
        }

        // ---- store prefetched x for next iteration ----
        if (hasnext) {
            #pragma unroll
            for (int kk = 0; kk < 3; kk++) {
                float4 v = (kk == 0) ? nx0 : (kk == 1) ? nx1 : nx2;
                int idx = tid + kk * 256;
                int row = idx >> 3, e4 = idx & 7;
                uint32_t o = (uint32_t)(row * 80 + e4 * 8);
                uint32_t h0, l0, h1, l1;
                splitw(v.x, v.y, h0, l0);
                splitw(v.z, v.w, h1, l1);
                *(uint32_t*)(smc + O_X_H + o)     = h0;
                *(uint32_t*)(smc + O_X_H + o + 4) = h1;
                *(uint32_t*)(smc + O_X_L + o)     = l0;
                *(uint32_t*)(smc + O_X_L + o + 4) = l1;
            }
        }
        __syncthreads();
    }
}

// ---------------- Kernel B: MLP with weight-reuse tiling (16 rows/iter) ----------------
// smem floats: sW1 0 (16384), sW2 16384 (32768), sb1 49152 (256), sb2 49408 (128),
//   sb3 49536 (16), sIn 49552 (16*65=1040), sZ1 50592 (16*261=4176),
//   sZ2 54768 (16*132=2112)  -> 56880 floats = 227520 B
#define SMEM_B_FLOATS 56880

__global__ void __launch_bounds__(256, 1)
kernelB(const float* __restrict__ W1, const float* __restrict__ b1,
        const float* __restrict__ W2, const float* __restrict__ b2,
        const float* __restrict__ W3, const float* __restrict__ b3,
        float* __restrict__ out)
{
    extern __shared__ float sm[];
    float* sW1 = sm;
    float* sW2 = sm + 16384;
    float* sb1 = sm + 49152;
    float* sb2 = sm + 49408;
    float* sb3 = sm + 49536;
    float* sIn = sm + 49552;   // [16][65]
    float* sZ1 = sm + 50592;   // [16][261]
    float* sZ2 = sm + 54768;   // [16][132]

    const int tid  = threadIdx.x;
    const int wid  = tid >> 5;
    const int lane = tid & 31;

    for (int i = tid; i < 16384; i += 256) sW1[i] = W1[i];
    for (int i = tid; i < 32768; i += 256) sW2[i] = W2[i];
    if (tid < 256) sb1[tid] = b1[tid];
    if (tid < 128) sb2[tid] = b2[tid];
    if (tid < 12)  sb3[tid] = b3[tid];
    __syncthreads();

    // layer1 map: warp cols wid*32 + (lane&7)*4 ; rows (lane>>3)+4j, j=0..3
    const int l1_c4 = lane & 7;
    const int l1_r  = lane >> 3;
    const int l1_cb = wid * 32;
    // layer2 map: warp cols wid*16 + (lane&3)*4 ; rows (lane>>2), +8
    const int l2_c4 = lane & 3;
    const int l2_r  = lane >> 2;
    const int l2_cb = wid * 16;

    for (int base = blockIdx.x * 16; base < SEQS; base += gridDim.x * 16) {
        // stage 16 rows of g_last -> sIn [16][65]
        {
            float4 v = ((const float4*)(g_last + (size_t)base * C1))[tid];
            int row = tid >> 4, e4 = tid & 15;
            float* d = sIn + row * 65 + e4 * 4;
            d[0] = v.x; d[1] = v.y; d[2] = v.z; d[3] = v.w;
        }
        __syncthreads();

        // ---- z1 = relu(in @ W1 + b1): 16 x 256 ----
        {
            float4 bb = ((const float4*)(sb1 + l1_cb))[l1_c4];
            float acc[4][4];
            #pragma unroll
            for (int j = 0; j < 4; j++) {
                acc[j][0] = bb.x; acc[j][1] = bb.y; acc[j][2] = bb.z; acc[j][3] = bb.w;
            }
            #pragma unroll 8
            for (int f = 0; f < 64; f++) {
                float4 w = ((const float4*)(sW1 + f * H1 + l1_cb))[l1_c4];
                float a0 = sIn[l1_r * 65 + f];
                float a1 = sIn[(l1_r + 4) * 65 + f];
                float a2 = sIn[(l1_r + 8) * 65 + f];
                float a3 = sIn[(l1_r + 12) * 65 + f];
                acc[0][0] += a0 * w.x; acc[0][1] += a0 * w.y; acc[0][2] += a0 * w.z; acc[0][3] += a0 * w.w;
                acc[1][0] += a1 * w.x; acc[1][1] += a1 * w.y; acc[1][2] += a1 * w.z; acc[1][3] += a1 * w.w;
                acc[2][0] += a2 * w.x; acc[2][1] += a2 * w.y; acc[2][2] += a2 * w.z; acc[2][3] += a2 * w.w;
                acc[3][0] += a3 * w.x; acc[3][1] += a3 * w.y; acc[3][2] += a3 * w.z; acc[3][3] += a3 * w.w;
            }
            #pragma unroll
            for (int j = 0; j < 4; j++) {
                float* d = sZ1 + (l1_r + 4 * j) * 261 + l1_cb + l1_c4 * 4;
                d[0] = fmaxf(acc[j][0], 0.f);
                d[1] = fmaxf(acc[j][1], 0.f);
                d[2] = fmaxf(acc[j][2], 0.f);
                d[3] = fmaxf(acc[j][3], 0.f);
            }
        }
        __syncthreads();

        // ---- z2 = relu(z1 @ W2 + b2): 16 x 128 ----
        {
            float4 bb = ((const float4*)(sb2 + l2_cb))[l2_c4];
            float a0[4] = {bb.x, bb.y, bb.z, bb.w};
            float a1[4] = {bb.x, bb.y, bb.z, bb.w};
            #pragma unroll 8
            for (int f = 0; f < 256; f++) {
                float4 w = ((const float4*)(sW2 + f * H2 + l2_cb))[l2_c4];
                float z0 = sZ1[l2_r * 261 + f];
                float z1 = sZ1[(l2_r + 8) * 261 + f];
                a0[0] += z0 * w.x; a0[1] += z0 * w.y; a0[2] += z0 * w.z; a0[3] += z0 * w.w;
                a1[0] += z1 * w.x; a1[1] += z1 * w.y; a1[2] += z1 * w.z; a1[3] += z1 * w.w;
            }
            ((float4*)(sZ2 + l2_r * 132 + l2_cb))[l2_c4] =
                make_float4(fmaxf(a0[0], 0.f), fmaxf(a0[1], 0.f), fmaxf(a0[2], 0.f), fmaxf(a0[3], 0.f));
            ((float4*)(sZ2 + (l2_r + 8) * 132 + l2_cb))[l2_c4] =
                make_float4(fmaxf(a1[0], 0.f), fmaxf(a1[1], 0.f), fmaxf(a1[2], 0.f), fmaxf(a1[3], 0.f));
        }
        __syncthreads();

        // ---- pred = z2 @ W3 + b3: 16 x 12, transposed write; W3 via L1 ----
        if (tid < 192) {
            int r = tid / 12, p = tid % 12;
            const float* zr = sZ2 + r * 132;
            float a = sb3[p];
            #pragma unroll 16
            for (int f = 0; f < 128; f++) a += zr[f] * __ldg(&W3[f * NPRED + p]);
            int seqr = base + r;
            int bb = seqr >> 11;
            int nn = seqr & 2047;
            out[(size_t)bb * (NPRED * 2048) + p * 2048 + nn] = a;
        }
        __syncthreads();
    }
}

extern "C" void kernel_launch(void* const* d_in, const int* in_sizes, int n_in,
                              void* d_out, int out_size)
{
    const float* x     = (const float*)d_in[0];
    const float* W_in  = (const float*)d_in[1];
    const float* b_in  = (const float*)d_in[2];
    const float* W_c   = (const float*)d_in[3];
    const float* b_c   = (const float*)d_in[4];
    const float* Wq    = (const float*)d_in[5];
    const float* bq    = (const float*)d_in[6];
    const float* Wk    = (const float*)d_in[7];
    const float* bk    = (const float*)d_in[8];
    const float* Wv    = (const float*)d_in[9];
    const float* bv    = (const float*)d_in[10];
    const float* W1    = (const float*)d_in[11];
    const float* b1    = (const float*)d_in[12];
    const float* W2    = (const float*)d_in[13];
    const float* b2    = (const float*)d_in[14];
    const float* W3    = (const float*)d_in[15];
    const float* b3    = (const float*)d_in[16];

    size_t smemB = SMEM_B_FLOATS * sizeof(float);
    cudaFuncSetAttribute(kernelA, cudaFuncAttributeMaxDynamicSharedMemorySize, SMEM_A);
    cudaFuncSetAttribute(kernelB, cudaFuncAttributeMaxDynamicSharedMemorySize, (int)smemB);

    kernelA<<<152, 256, SMEM_A>>>(x, W_in, b_in, W_c, b_c, Wq, bq, Wk, bk, Wv, bv);
    kernelB<<<152, 256, smemB>>>(W1, b1, W2, b2, W3, b3, (float*)d_out);
}